// round 1
// baseline (speedup 1.0000x reference)
#include <cuda_runtime.h>
#include <cuda_bf16.h>
#include <cstddef>

#define B_ 2
#define L_ 1920
#define D_ 512
#define H_ 8
#define DH_ 64
#define BH_ (B_*H_)
#define OUT_ELEMS (B_*L_*D_)      // 1966080
#define ATTN_ELEMS (BH_*L_*L_)    // 58982400

// Scratch buffers (device globals per harness rules; no cudaMalloc allowed)
__device__ float g_qp[B_*L_*D_];
__device__ float g_kp[B_*L_*D_];
__device__ float g_vp[B_*L_*D_];
__device__ float g_o [BH_*L_*DH_];

// ---------------------------------------------------------------------------
// Fused QKV projection: z in blockIdx.z selects which of the three GEMMs.
// C[M=3840, N=512] = A[3840,512] @ W[512,512] + bias
// ---------------------------------------------------------------------------
__global__ __launch_bounds__(256)
void qkv_proj_kernel(const float* __restrict__ q, const float* __restrict__ k,
                     const float* __restrict__ v,
                     const float* __restrict__ Wq, const float* __restrict__ Wk,
                     const float* __restrict__ Wv,
                     const float* __restrict__ bq, const float* __restrict__ bk,
                     const float* __restrict__ bv)
{
    const float* A; const float* W; const float* bias; float* C;
    int z = blockIdx.z;
    if (z == 0)      { A = q; W = Wq; bias = bq; C = g_qp; }
    else if (z == 1) { A = k; W = Wk; bias = bk; C = g_kp; }
    else             { A = v; W = Wv; bias = bv; C = g_vp; }

    __shared__ float As[16][65];
    __shared__ float Bs[16][65];
    int tid = threadIdx.x;
    int tx = tid & 15, ty = tid >> 4;
    int m0 = blockIdx.y * 64, n0 = blockIdx.x * 64;
    float acc[4][4] = {};

    for (int k0 = 0; k0 < 512; k0 += 16) {
        #pragma unroll
        for (int r = 0; r < 4; r++) {
            int idx = tid + r * 256;
            int kk = idx & 15, m = idx >> 4;
            As[kk][m] = A[(size_t)(m0 + m) * 512 + k0 + kk];
        }
        #pragma unroll
        for (int r = 0; r < 4; r++) {
            int idx = tid + r * 256;
            int n = idx & 63, kk = idx >> 6;
            Bs[kk][n] = W[(size_t)(k0 + kk) * 512 + n0 + n];
        }
        __syncthreads();
        #pragma unroll
        for (int kk = 0; kk < 16; kk++) {
            float a[4], b[4];
            #pragma unroll
            for (int i = 0; i < 4; i++) a[i] = As[kk][ty * 4 + i];
            #pragma unroll
            for (int j = 0; j < 4; j++) b[j] = Bs[kk][tx * 4 + j];
            #pragma unroll
            for (int i = 0; i < 4; i++)
                #pragma unroll
                for (int j = 0; j < 4; j++)
                    acc[i][j] += a[i] * b[j];
        }
        __syncthreads();
    }
    #pragma unroll
    for (int i = 0; i < 4; i++)
        #pragma unroll
        for (int j = 0; j < 4; j++)
            C[(size_t)(m0 + ty * 4 + i) * 512 + n0 + tx * 4 + j] =
                acc[i][j] + bias[n0 + tx * 4 + j];
}

// ---------------------------------------------------------------------------
// Fused scores: logits[q,k] = (Q.K[k] + Q.E[1 + k-q+L-1]) * 0.125
// Only causal tiles (kt <= qt) are computed; non-causal entries are zeroed by
// the softmax kernel (they underflow to exact 0 in the reference too).
// ---------------------------------------------------------------------------
__global__ __launch_bounds__(256)
void scores_kernel(const float* __restrict__ E, float* __restrict__ attn)
{
    int kt = blockIdx.x, qt = blockIdx.y;
    if (kt > qt) return;
    int bh = blockIdx.z;
    int b = bh >> 3, h = bh & 7;
    int q0 = qt * 64, k0 = kt * 64;

    __shared__ float Qs[16][65];
    __shared__ float Ks[16][65];
    __shared__ float Es[16][129];

    int tid = threadIdx.x;
    int tx = tid & 15, ty = tid >> 4;
    float acc[4][4] = {};

    const float* qbase = g_qp + (size_t)b * L_ * 512 + h * 64;
    const float* kbase = g_kp + (size_t)b * L_ * 512 + h * 64;
    // absolute rel row: r = (k-q) + (L-1); with roff = (k-q)-(k0-q0)+63 in [0,126]
    // r = k0 - q0 + 1856 + roff ; valid rows 0..1919, e = E[1:]
    int rbase = k0 - q0 + 1856;

    for (int dc = 0; dc < 4; dc++) {
        int d0 = dc * 16;
        #pragma unroll
        for (int r = 0; r < 4; r++) {
            int idx = tid + r * 256;
            int dd = idx & 15, m = idx >> 4;
            Qs[dd][m] = qbase[(size_t)(q0 + m) * 512 + d0 + dd];
            Ks[dd][m] = kbase[(size_t)(k0 + m) * 512 + d0 + dd];
        }
        #pragma unroll
        for (int r = 0; r < 8; r++) {
            int idx = tid + r * 256;
            int dd = idx & 15, ro = idx >> 4;       // ro in [0,127]
            int rr = rbase + ro;
            Es[dd][ro] = (rr >= 0 && rr < L_)
                       ? E[(size_t)(rr + 1) * 512 + h * 64 + d0 + dd] : 0.f;
        }
        __syncthreads();
        int ebase = 4 * (tx - ty) + 60;             // + (j-i+3) => roff
        #pragma unroll
        for (int dd = 0; dd < 16; dd++) {
            float a[4], kv[4], ev[7];
            #pragma unroll
            for (int i = 0; i < 4; i++) a[i] = Qs[dd][ty * 4 + i];
            #pragma unroll
            for (int j = 0; j < 4; j++) kv[j] = Ks[dd][tx * 4 + j];
            #pragma unroll
            for (int t = 0; t < 7; t++) ev[t] = Es[dd][ebase + t];
            #pragma unroll
            for (int i = 0; i < 4; i++)
                #pragma unroll
                for (int j = 0; j < 4; j++)
                    acc[i][j] += a[i] * (kv[j] + ev[j - i + 3]);
        }
        __syncthreads();
    }

    float* out = attn + ((size_t)bh * L_ + q0) * L_ + k0;
    #pragma unroll
    for (int i = 0; i < 4; i++)
        #pragma unroll
        for (int j = 0; j < 4; j++)
            out[(size_t)(ty * 4 + i) * L_ + tx * 4 + j] = acc[i][j] * 0.125f;
}

// ---------------------------------------------------------------------------
// Causal row softmax in-place; zeros for k > q (matches fp32 underflow in ref)
// ---------------------------------------------------------------------------
__global__ __launch_bounds__(256)
void softmax_kernel(float* __restrict__ attn)
{
    int p = blockIdx.x;           // p = bh*L + q
    int q = p % L_;
    int n = q + 1;
    float* row = attn + (size_t)p * L_;

    __shared__ float buf[L_];
    __shared__ float red[256];
    int tid = threadIdx.x;

    float mx = -1e30f;
    for (int k = tid; k < n; k += 256) {
        float v = row[k];
        buf[k] = v;
        mx = fmaxf(mx, v);
    }
    red[tid] = mx;
    __syncthreads();
    for (int s = 128; s > 0; s >>= 1) {
        if (tid < s) red[tid] = fmaxf(red[tid], red[tid + s]);
        __syncthreads();
    }
    mx = red[0];
    __syncthreads();

    float sm = 0.f;
    for (int k = tid; k < n; k += 256) {
        float e = __expf(buf[k] - mx);
        buf[k] = e;
        sm += e;
    }
    red[tid] = sm;
    __syncthreads();
    for (int s = 128; s > 0; s >>= 1) {
        if (tid < s) red[tid] += red[tid + s];
        __syncthreads();
    }
    float inv = 1.f / red[0];

    for (int k = tid; k < n; k += 256)      row[k] = buf[k] * inv;
    for (int k = n + tid; k < L_; k += 256) row[k] = 0.f;
}

// ---------------------------------------------------------------------------
// O = attn @ Vh  (per b,h). Causal loop bound: rows in tile qt only need
// k < q0+64 (rest of the row is exact zeros).
// ---------------------------------------------------------------------------
__global__ __launch_bounds__(256)
void av_kernel(const float* __restrict__ attn)
{
    int qt = blockIdx.x;
    int bh = blockIdx.y;
    int b = bh >> 3, h = bh & 7;
    int q0 = qt * 64;

    __shared__ float As[16][65];   // [kk][q_local]
    __shared__ float Bs[16][65];   // [kk][dh]
    int tid = threadIdx.x;
    int tx = tid & 15, ty = tid >> 4;
    float acc[4][4] = {};

    const float* arow  = attn + ((size_t)bh * L_ + q0) * L_;
    const float* vbase = g_vp + (size_t)b * L_ * 512 + h * 64;
    int kend = q0 + 64;

    for (int k0 = 0; k0 < kend; k0 += 16) {
        #pragma unroll
        for (int r = 0; r < 4; r++) {
            int idx = tid + r * 256;
            int kk = idx & 15, m = idx >> 4;
            As[kk][m] = arow[(size_t)m * L_ + k0 + kk];
        }
        #pragma unroll
        for (int r = 0; r < 4; r++) {
            int idx = tid + r * 256;
            int n = idx & 63, kk = idx >> 6;
            Bs[kk][n] = vbase[(size_t)(k0 + kk) * 512 + n];
        }
        __syncthreads();
        #pragma unroll
        for (int kk = 0; kk < 16; kk++) {
            float a[4], bv[4];
            #pragma unroll
            for (int i = 0; i < 4; i++) a[i] = As[kk][ty * 4 + i];
            #pragma unroll
            for (int j = 0; j < 4; j++) bv[j] = Bs[kk][tx * 4 + j];
            #pragma unroll
            for (int i = 0; i < 4; i++)
                #pragma unroll
                for (int j = 0; j < 4; j++)
                    acc[i][j] += a[i] * bv[j];
        }
        __syncthreads();
    }
    #pragma unroll
    for (int i = 0; i < 4; i++)
        #pragma unroll
        for (int j = 0; j < 4; j++)
            g_o[((size_t)bh * L_ + q0 + ty * 4 + i) * 64 + tx * 4 + j] = acc[i][j];
}

// ---------------------------------------------------------------------------
// Final projection with head-recombine gather:
// out[b,l,:] = concat_h(o[b,h,l,:]) @ Wo + bo
// ---------------------------------------------------------------------------
__global__ __launch_bounds__(256)
void oproj_kernel(const float* __restrict__ Wo, const float* __restrict__ bo,
                  float* __restrict__ out)
{
    __shared__ float As[16][65];
    __shared__ float Bs[16][65];
    int tid = threadIdx.x;
    int tx = tid & 15, ty = tid >> 4;
    int m0 = blockIdx.y * 64, n0 = blockIdx.x * 64;
    int b = m0 / L_;               // tiles never straddle the batch boundary
    int l0 = m0 - b * L_;
    float acc[4][4] = {};

    for (int k0 = 0; k0 < 512; k0 += 16) {
        #pragma unroll
        for (int r = 0; r < 4; r++) {
            int idx = tid + r * 256;
            int kk = idx & 15, m = idx >> 4;
            int kidx = k0 + kk;
            int h = kidx >> 6, dh = kidx & 63;
            As[kk][m] = g_o[((size_t)(b * 8 + h) * L_ + l0 + m) * 64 + dh];
        }
        #pragma unroll
        for (int r = 0; r < 4; r++) {
            int idx = tid + r * 256;
            int n = idx & 63, kk = idx >> 6;
            Bs[kk][n] = Wo[(size_t)(k0 + kk) * 512 + n0 + n];
        }
        __syncthreads();
        #pragma unroll
        for (int kk = 0; kk < 16; kk++) {
            float a[4], bv[4];
            #pragma unroll
            for (int i = 0; i < 4; i++) a[i] = As[kk][ty * 4 + i];
            #pragma unroll
            for (int j = 0; j < 4; j++) bv[j] = Bs[kk][tx * 4 + j];
            #pragma unroll
            for (int i = 0; i < 4; i++)
                #pragma unroll
                for (int j = 0; j < 4; j++)
                    acc[i][j] += a[i] * bv[j];
        }
        __syncthreads();
    }
    #pragma unroll
    for (int i = 0; i < 4; i++)
        #pragma unroll
        for (int j = 0; j < 4; j++)
            out[(size_t)(m0 + ty * 4 + i) * 512 + n0 + tx * 4 + j] =
                acc[i][j] + bo[n0 + tx * 4 + j];
}

// ---------------------------------------------------------------------------
extern "C" void kernel_launch(void* const* d_in, const int* in_sizes, int n_in,
                              void* d_out, int out_size)
{
    const float* q  = (const float*)d_in[0];
    const float* k  = (const float*)d_in[1];
    const float* v  = (const float*)d_in[2];
    // d_in[3] = mask (unused: causality handled analytically)
    const float* Wq = (const float*)d_in[4];
    const float* bq = (const float*)d_in[5];
    const float* Wk = (const float*)d_in[6];
    const float* bk = (const float*)d_in[7];
    const float* Wv = (const float*)d_in[8];
    const float* bv = (const float*)d_in[9];
    const float* E  = (const float*)d_in[10];
    const float* Wo = (const float*)d_in[11];
    const float* bo = (const float*)d_in[12];

    float* out_ptr  = (float*)d_out;
    float* attn_ptr = out_ptr + OUT_ELEMS;   // tuple order: (out, attn)

    // 1) Q/K/V projections (one launch, z selects target)
    qkv_proj_kernel<<<dim3(8, 60, 3), 256>>>(q, k, v, Wq, Wk, Wv, bq, bk, bv);

    // 2) fused QK^T + skewed relative scores (causal tiles only)
    scores_kernel<<<dim3(30, 30, 16), 256>>>(E, attn_ptr);

    // 3) causal softmax in-place (writes the attn output)
    softmax_kernel<<<BH_ * L_, 256>>>(attn_ptr);

    // 4) O = attn @ V
    av_kernel<<<dim3(30, 16), 256>>>(attn_ptr);

    // 5) output projection
    oproj_kernel<<<dim3(8, 60), 256>>>(Wo, bo, out_ptr);
}

// round 2
// speedup vs baseline: 1.4350x; 1.4350x over previous
#include <cuda_runtime.h>
#include <cuda_bf16.h>
#include <cstddef>

#define B_ 2
#define L_ 1920
#define D_ 512
#define H_ 8
#define DH_ 64
#define BH_ (B_*H_)
#define OUT_ELEMS (B_*L_*D_)      // 1966080
#define ATTN_ELEMS (BH_*L_*L_)    // 58982400
#define NSPLIT 4
#define SPLITW 480                // k columns per av split (30 x 16)

// Scratch (device globals; no cudaMalloc allowed)
__device__ float g_qp[B_*L_*D_];
__device__ float g_kp[B_*L_*D_];
__device__ float g_vp[B_*L_*D_];
__device__ float g_op[NSPLIT * BH_*L_*DH_];   // av split-K partials

// ---------------------------------------------------------------------------
// Fused QKV projection: blockIdx.z selects target GEMM.
// ---------------------------------------------------------------------------
__global__ __launch_bounds__(256)
void qkv_proj_kernel(const float* __restrict__ q, const float* __restrict__ k,
                     const float* __restrict__ v,
                     const float* __restrict__ Wq, const float* __restrict__ Wk,
                     const float* __restrict__ Wv,
                     const float* __restrict__ bq, const float* __restrict__ bk,
                     const float* __restrict__ bv)
{
    const float* A; const float* W; const float* bias; float* C;
    int z = blockIdx.z;
    if (z == 0)      { A = q; W = Wq; bias = bq; C = g_qp; }
    else if (z == 1) { A = k; W = Wk; bias = bk; C = g_kp; }
    else             { A = v; W = Wv; bias = bv; C = g_vp; }

    __shared__ float As[16][68];
    __shared__ float Bs[16][68];
    int tid = threadIdx.x;
    int tx = tid & 15, ty = tid >> 4;
    int m0 = blockIdx.y * 64, n0 = blockIdx.x * 64;
    float acc[4][4] = {};

    int mA = tid >> 2, gA = tid & 3;       // A: row mA, float4 group gA
    int kB = tid >> 4, gB = tid & 15;      // W: row kB, float4 group gB

    for (int k0 = 0; k0 < 512; k0 += 16) {
        float4 av = *(const float4*)(A + (size_t)(m0 + mA) * 512 + k0 + gA * 4);
        As[gA*4+0][mA] = av.x; As[gA*4+1][mA] = av.y;
        As[gA*4+2][mA] = av.z; As[gA*4+3][mA] = av.w;
        float4 wv = *(const float4*)(W + (size_t)(k0 + kB) * 512 + n0 + gB * 4);
        Bs[kB][gB*4+0] = wv.x; Bs[kB][gB*4+1] = wv.y;
        Bs[kB][gB*4+2] = wv.z; Bs[kB][gB*4+3] = wv.w;
        __syncthreads();
        #pragma unroll
        for (int kk = 0; kk < 16; kk++) {
            float a[4], b[4];
            #pragma unroll
            for (int i = 0; i < 4; i++) a[i] = As[kk][ty * 4 + i];
            #pragma unroll
            for (int j = 0; j < 4; j++) b[j] = Bs[kk][tx * 4 + j];
            #pragma unroll
            for (int i = 0; i < 4; i++)
                #pragma unroll
                for (int j = 0; j < 4; j++)
                    acc[i][j] += a[i] * b[j];
        }
        __syncthreads();
    }
    #pragma unroll
    for (int i = 0; i < 4; i++) {
        float4 o;
        o.x = acc[i][0] + bias[n0 + tx*4 + 0];
        o.y = acc[i][1] + bias[n0 + tx*4 + 1];
        o.z = acc[i][2] + bias[n0 + tx*4 + 2];
        o.w = acc[i][3] + bias[n0 + tx*4 + 3];
        *(float4*)(C + (size_t)(m0 + ty*4 + i) * 512 + n0 + tx*4) = o;
    }
}

// ---------------------------------------------------------------------------
// Fused scores: logits[q,k] = (Q.K[k] + Q.E[1 + k-q+L-1]) * 0.125
// Triangular grid: blockIdx.x in [0,465) enumerates causal (qt,kt) pairs.
// ---------------------------------------------------------------------------
__global__ __launch_bounds__(256)
void scores_kernel(const float* __restrict__ E, float* __restrict__ attn)
{
    int idx = blockIdx.x;
    int qt = (int)((sqrtf(8.f * idx + 1.f) - 1.f) * 0.5f);
    while ((qt + 1) * (qt + 2) / 2 <= idx) qt++;
    while (qt * (qt + 1) / 2 > idx) qt--;
    int kt = idx - qt * (qt + 1) / 2;

    int bh = blockIdx.y;
    int b = bh >> 3, h = bh & 7;
    int q0 = qt * 64, k0 = kt * 64;

    __shared__ float Qs[16][68];
    __shared__ float Ks[16][68];
    __shared__ float Es[16][129];

    int tid = threadIdx.x;
    int tx = tid & 15, ty = tid >> 4;
    float acc[4][4] = {};

    const float* qbase = g_qp + (size_t)b * L_ * 512 + h * 64;
    const float* kbase = g_kp + (size_t)b * L_ * 512 + h * 64;
    int rbase = k0 - q0 + 1856;

    int mA = tid >> 2, gA = tid & 3;

    for (int dc = 0; dc < 4; dc++) {
        int d0 = dc * 16;
        {
            float4 qv = *(const float4*)(qbase + (size_t)(q0 + mA) * 512 + d0 + gA * 4);
            Qs[gA*4+0][mA] = qv.x; Qs[gA*4+1][mA] = qv.y;
            Qs[gA*4+2][mA] = qv.z; Qs[gA*4+3][mA] = qv.w;
            float4 kv = *(const float4*)(kbase + (size_t)(k0 + mA) * 512 + d0 + gA * 4);
            Ks[gA*4+0][mA] = kv.x; Ks[gA*4+1][mA] = kv.y;
            Ks[gA*4+2][mA] = kv.z; Ks[gA*4+3][mA] = kv.w;
        }
        #pragma unroll
        for (int r = 0; r < 2; r++) {
            int i2 = tid + r * 256;            // 0..511
            int ro = i2 >> 2, g = i2 & 3;      // ro 0..127
            int rr = rbase + ro;
            float4 ev = make_float4(0.f, 0.f, 0.f, 0.f);
            if (rr >= 0 && rr < L_)
                ev = *(const float4*)(E + (size_t)(rr + 1) * 512 + h * 64 + d0 + g * 4);
            Es[g*4+0][ro] = ev.x; Es[g*4+1][ro] = ev.y;
            Es[g*4+2][ro] = ev.z; Es[g*4+3][ro] = ev.w;
        }
        __syncthreads();
        int ebase = 4 * (tx - ty) + 60;
        #pragma unroll
        for (int dd = 0; dd < 16; dd++) {
            float a[4], kv[4], ev[7];
            #pragma unroll
            for (int i = 0; i < 4; i++) a[i] = Qs[dd][ty * 4 + i];
            #pragma unroll
            for (int j = 0; j < 4; j++) kv[j] = Ks[dd][tx * 4 + j];
            #pragma unroll
            for (int t = 0; t < 7; t++) ev[t] = Es[dd][ebase + t];
            #pragma unroll
            for (int i = 0; i < 4; i++)
                #pragma unroll
                for (int j = 0; j < 4; j++)
                    acc[i][j] += a[i] * (kv[j] + ev[j - i + 3]);
        }
        __syncthreads();
    }

    float* out = attn + ((size_t)bh * L_ + q0) * L_ + k0;
    #pragma unroll
    for (int i = 0; i < 4; i++) {
        float4 o;
        o.x = acc[i][0] * 0.125f; o.y = acc[i][1] * 0.125f;
        o.z = acc[i][2] * 0.125f; o.w = acc[i][3] * 0.125f;
        *(float4*)(out + (size_t)(ty*4 + i) * L_ + tx*4) = o;
    }
}

// ---------------------------------------------------------------------------
// Causal row softmax in-place, float4 throughout; zeros for k > q.
// ---------------------------------------------------------------------------
__global__ __launch_bounds__(256)
void softmax_kernel(float* __restrict__ attn)
{
    int p = blockIdx.x;           // p = bh*L + q
    int q = p % L_;
    int n = q + 1;
    int nv = (n + 3) >> 2;        // quads containing valid data
    float4* row = (float4*)(attn + (size_t)p * L_);

    __shared__ float4 buf[L_/4];
    __shared__ float red[256];
    int tid = threadIdx.x;

    float mx = -1e30f;
    for (int i = tid; i < nv; i += 256) {
        float4 v = row[i];
        int base = i * 4;
        if (base + 1 >= n) v.y = -1e30f;
        if (base + 2 >= n) v.z = -1e30f;
        if (base + 3 >= n) v.w = -1e30f;
        buf[i] = v;
        mx = fmaxf(mx, fmaxf(fmaxf(v.x, v.y), fmaxf(v.z, v.w)));
    }
    red[tid] = mx;
    __syncthreads();
    #pragma unroll
    for (int s = 128; s > 0; s >>= 1) {
        if (tid < s) red[tid] = fmaxf(red[tid], red[tid + s]);
        __syncthreads();
    }
    mx = red[0];
    __syncthreads();

    float sm = 0.f;
    for (int i = tid; i < nv; i += 256) {
        float4 v = buf[i];
        v.x = __expf(v.x - mx); v.y = __expf(v.y - mx);
        v.z = __expf(v.z - mx); v.w = __expf(v.w - mx);
        buf[i] = v;
        sm += v.x + v.y + v.z + v.w;
    }
    red[tid] = sm;
    __syncthreads();
    #pragma unroll
    for (int s = 128; s > 0; s >>= 1) {
        if (tid < s) red[tid] += red[tid + s];
        __syncthreads();
    }
    float inv = 1.f / red[0];

    for (int i = tid; i < nv; i += 256) {
        float4 v = buf[i];
        v.x *= inv; v.y *= inv; v.z *= inv; v.w *= inv;
        row[i] = v;
    }
    float4 z4 = make_float4(0.f, 0.f, 0.f, 0.f);
    for (int i = nv + tid; i < L_/4; i += 256) row[i] = z4;
}

// ---------------------------------------------------------------------------
// O_partial[s] = attn[:, kbeg:kend] @ V[kbeg:kend]  (split-K for balance)
// ---------------------------------------------------------------------------
__global__ __launch_bounds__(256)
void av_kernel(const float* __restrict__ attn)
{
    int qt = blockIdx.x;
    int bh = blockIdx.y;
    int s  = blockIdx.z;
    int b = bh >> 3, h = bh & 7;
    int q0 = qt * 64;

    int kbeg = s * SPLITW;
    int kend = min(q0 + 64, kbeg + SPLITW);
    if (kbeg >= kend) return;

    __shared__ float As[16][68];   // [kk][q_local]
    __shared__ float Bs[16][68];   // [kk][dh]
    int tid = threadIdx.x;
    int tx = tid & 15, ty = tid >> 4;
    float acc[4][4] = {};

    const float* arow  = attn + ((size_t)bh * L_ + q0) * L_;
    const float* vbase = g_vp + (size_t)b * L_ * 512 + h * 64;

    int mA = tid >> 2, gA = tid & 3;
    int kB = tid >> 4, gB = tid & 15;

    for (int k0 = kbeg; k0 < kend; k0 += 16) {
        float4 av = *(const float4*)(arow + (size_t)mA * L_ + k0 + gA * 4);
        As[gA*4+0][mA] = av.x; As[gA*4+1][mA] = av.y;
        As[gA*4+2][mA] = av.z; As[gA*4+3][mA] = av.w;
        float4 vv = *(const float4*)(vbase + (size_t)(k0 + kB) * 512 + gB * 4);
        Bs[kB][gB*4+0] = vv.x; Bs[kB][gB*4+1] = vv.y;
        Bs[kB][gB*4+2] = vv.z; Bs[kB][gB*4+3] = vv.w;
        __syncthreads();
        #pragma unroll
        for (int kk = 0; kk < 16; kk++) {
            float a[4], bv[4];
            #pragma unroll
            for (int i = 0; i < 4; i++) a[i] = As[kk][ty * 4 + i];
            #pragma unroll
            for (int j = 0; j < 4; j++) bv[j] = Bs[kk][tx * 4 + j];
            #pragma unroll
            for (int i = 0; i < 4; i++)
                #pragma unroll
                for (int j = 0; j < 4; j++)
                    acc[i][j] += a[i] * bv[j];
        }
        __syncthreads();
    }

    float* op = g_op + (size_t)s * (BH_*L_*DH_) + ((size_t)bh * L_ + q0) * 64;
    #pragma unroll
    for (int i = 0; i < 4; i++) {
        float4 o;
        o.x = acc[i][0]; o.y = acc[i][1]; o.z = acc[i][2]; o.w = acc[i][3];
        *(float4*)(op + (size_t)(ty*4 + i) * 64 + tx*4) = o;
    }
}

// ---------------------------------------------------------------------------
// out[b,l,:] = (sum_s O_partial[s][b,:,l,:] gathered across heads) @ Wo + bo
// ---------------------------------------------------------------------------
__global__ __launch_bounds__(256)
void oproj_kernel(const float* __restrict__ Wo, const float* __restrict__ bo,
                  float* __restrict__ out)
{
    __shared__ float As[16][68];
    __shared__ float Bs[16][68];
    int tid = threadIdx.x;
    int tx = tid & 15, ty = tid >> 4;
    int m0 = blockIdx.y * 64, n0 = blockIdx.x * 64;
    int b = m0 / L_;
    int l0 = m0 - b * L_;
    float acc[4][4] = {};

    // number of av splits that produced partials for this q-tile
    int ns = (l0 + 64 + SPLITW - 1) / SPLITW;

    int mA = tid >> 2, gA = tid & 3;
    int kB = tid >> 4, gB = tid & 15;

    for (int k0 = 0; k0 < 512; k0 += 16) {
        int h = k0 >> 6, dh0 = k0 & 63;
        {
            const float* base = g_op + (((size_t)(b*8 + h) * L_ + l0 + mA) * 64 + dh0 + gA*4);
            float4 a4 = *(const float4*)(base);
            for (int ss = 1; ss < ns; ss++) {
                float4 t = *(const float4*)(base + (size_t)ss * (BH_*L_*DH_));
                a4.x += t.x; a4.y += t.y; a4.z += t.z; a4.w += t.w;
            }
            As[gA*4+0][mA] = a4.x; As[gA*4+1][mA] = a4.y;
            As[gA*4+2][mA] = a4.z; As[gA*4+3][mA] = a4.w;
        }
        float4 wv = *(const float4*)(Wo + (size_t)(k0 + kB) * 512 + n0 + gB * 4);
        Bs[kB][gB*4+0] = wv.x; Bs[kB][gB*4+1] = wv.y;
        Bs[kB][gB*4+2] = wv.z; Bs[kB][gB*4+3] = wv.w;
        __syncthreads();
        #pragma unroll
        for (int kk = 0; kk < 16; kk++) {
            float a[4], bv[4];
            #pragma unroll
            for (int i = 0; i < 4; i++) a[i] = As[kk][ty * 4 + i];
            #pragma unroll
            for (int j = 0; j < 4; j++) bv[j] = Bs[kk][tx * 4 + j];
            #pragma unroll
            for (int i = 0; i < 4; i++)
                #pragma unroll
                for (int j = 0; j < 4; j++)
                    acc[i][j] += a[i] * bv[j];
        }
        __syncthreads();
    }
    #pragma unroll
    for (int i = 0; i < 4; i++) {
        float4 o;
        o.x = acc[i][0] + bo[n0 + tx*4 + 0];
        o.y = acc[i][1] + bo[n0 + tx*4 + 1];
        o.z = acc[i][2] + bo[n0 + tx*4 + 2];
        o.w = acc[i][3] + bo[n0 + tx*4 + 3];
        *(float4*)(out + (size_t)(m0 + ty*4 + i) * 512 + n0 + tx*4) = o;
    }
}

// ---------------------------------------------------------------------------
extern "C" void kernel_launch(void* const* d_in, const int* in_sizes, int n_in,
                              void* d_out, int out_size)
{
    const float* q  = (const float*)d_in[0];
    const float* k  = (const float*)d_in[1];
    const float* v  = (const float*)d_in[2];
    const float* Wq = (const float*)d_in[4];
    const float* bq = (const float*)d_in[5];
    const float* Wk = (const float*)d_in[6];
    const float* bk = (const float*)d_in[7];
    const float* Wv = (const float*)d_in[8];
    const float* bv = (const float*)d_in[9];
    const float* E  = (const float*)d_in[10];
    const float* Wo = (const float*)d_in[11];
    const float* bo = (const float*)d_in[12];

    float* out_ptr  = (float*)d_out;
    float* attn_ptr = out_ptr + OUT_ELEMS;   // tuple order: (out, attn)

    qkv_proj_kernel<<<dim3(8, 60, 3), 256>>>(q, k, v, Wq, Wk, Wv, bq, bk, bv);
    scores_kernel<<<dim3(465, 16), 256>>>(E, attn_ptr);
    softmax_kernel<<<BH_ * L_, 256>>>(attn_ptr);
    av_kernel<<<dim3(30, 16, NSPLIT), 256>>>(attn_ptr);
    oproj_kernel<<<dim3(8, 60), 256>>>(Wo, bo, out_ptr);
}

// round 3
// speedup vs baseline: 1.5033x; 1.0476x over previous
#include <cuda_runtime.h>
#include <cuda_bf16.h>
#include <cstddef>

#define B_ 2
#define L_ 1920
#define D_ 512
#define H_ 8
#define DH_ 64
#define BH_ (B_*H_)
#define NT_ 30                    // 64-wide tiles per row
#define OUT_ELEMS (B_*L_*D_)      // 1966080
#define NSPLIT 4
#define SPLITW 480                // k columns per av split

// Scratch (device globals; no cudaMalloc allowed)
__device__ float g_qp[B_*L_*D_];
__device__ float g_kp[B_*L_*D_];
__device__ float g_vp[B_*L_*D_];
__device__ float g_op[NSPLIT * BH_*L_*DH_];     // av split-K partials
__device__ float2 g_stats[BH_*NT_*L_];          // per (bh,kt,q): tile max, tile sumexp
__device__ float g_M[BH_*L_];                   // per-row max
__device__ float g_I[BH_*L_];                   // per-row 1/sum

// ---------------------------------------------------------------------------
// Fused QKV projection: blockIdx.z selects target GEMM.
// ---------------------------------------------------------------------------
__global__ __launch_bounds__(256)
void qkv_proj_kernel(const float* __restrict__ q, const float* __restrict__ k,
                     const float* __restrict__ v,
                     const float* __restrict__ Wq, const float* __restrict__ Wk,
                     const float* __restrict__ Wv,
                     const float* __restrict__ bq, const float* __restrict__ bk,
                     const float* __restrict__ bv)
{
    const float* A; const float* W; const float* bias; float* C;
    int z = blockIdx.z;
    if (z == 0)      { A = q; W = Wq; bias = bq; C = g_qp; }
    else if (z == 1) { A = k; W = Wk; bias = bk; C = g_kp; }
    else             { A = v; W = Wv; bias = bv; C = g_vp; }

    __shared__ float As[16][68];
    __shared__ float Bs[16][68];
    int tid = threadIdx.x;
    int tx = tid & 15, ty = tid >> 4;
    int m0 = blockIdx.y * 64, n0 = blockIdx.x * 64;
    float acc[4][4] = {};

    int mA = tid >> 2, gA = tid & 3;
    int kB = tid >> 4, gB = tid & 15;

    for (int k0 = 0; k0 < 512; k0 += 16) {
        float4 av = *(const float4*)(A + (size_t)(m0 + mA) * 512 + k0 + gA * 4);
        As[gA*4+0][mA] = av.x; As[gA*4+1][mA] = av.y;
        As[gA*4+2][mA] = av.z; As[gA*4+3][mA] = av.w;
        float4 wv = *(const float4*)(W + (size_t)(k0 + kB) * 512 + n0 + gB * 4);
        Bs[kB][gB*4+0] = wv.x; Bs[kB][gB*4+1] = wv.y;
        Bs[kB][gB*4+2] = wv.z; Bs[kB][gB*4+3] = wv.w;
        __syncthreads();
        #pragma unroll
        for (int kk = 0; kk < 16; kk++) {
            float a[4], b[4];
            #pragma unroll
            for (int i = 0; i < 4; i++) a[i] = As[kk][ty * 4 + i];
            #pragma unroll
            for (int j = 0; j < 4; j++) b[j] = Bs[kk][tx * 4 + j];
            #pragma unroll
            for (int i = 0; i < 4; i++)
                #pragma unroll
                for (int j = 0; j < 4; j++)
                    acc[i][j] += a[i] * b[j];
        }
        __syncthreads();
    }
    #pragma unroll
    for (int i = 0; i < 4; i++) {
        float4 o;
        o.x = acc[i][0] + bias[n0 + tx*4 + 0];
        o.y = acc[i][1] + bias[n0 + tx*4 + 1];
        o.z = acc[i][2] + bias[n0 + tx*4 + 2];
        o.w = acc[i][3] + bias[n0 + tx*4 + 3];
        *(float4*)(C + (size_t)(m0 + ty*4 + i) * 512 + n0 + tx*4) = o;
    }
}

// ---------------------------------------------------------------------------
// Fused scores + per-tile softmax stats.
// logits[q,k] = (Q.K[k] + Q.E[1 + k-q+L-1]) * 0.125  (causal tiles only)
// Also writes (tile row max, tile row sumexp) to g_stats[bh][kt][q].
// ---------------------------------------------------------------------------
__global__ __launch_bounds__(256)
void scores_kernel(const float* __restrict__ E, float* __restrict__ attn)
{
    int idx = blockIdx.x;
    int qt = (int)((sqrtf(8.f * idx + 1.f) - 1.f) * 0.5f);
    while ((qt + 1) * (qt + 2) / 2 <= idx) qt++;
    while (qt * (qt + 1) / 2 > idx) qt--;
    int kt = idx - qt * (qt + 1) / 2;

    int bh = blockIdx.y;
    int b = bh >> 3, h = bh & 7;
    int q0 = qt * 64, k0 = kt * 64;

    __shared__ float Qs[16][68];
    __shared__ float Ks[16][68];
    __shared__ float Es[16][129];

    int tid = threadIdx.x;
    int tx = tid & 15, ty = tid >> 4;
    float acc[4][4] = {};

    const float* qbase = g_qp + (size_t)b * L_ * 512 + h * 64;
    const float* kbase = g_kp + (size_t)b * L_ * 512 + h * 64;
    int rbase = k0 - q0 + 1856;

    int mA = tid >> 2, gA = tid & 3;

    for (int dc = 0; dc < 4; dc++) {
        int d0 = dc * 16;
        {
            float4 qv = *(const float4*)(qbase + (size_t)(q0 + mA) * 512 + d0 + gA * 4);
            Qs[gA*4+0][mA] = qv.x; Qs[gA*4+1][mA] = qv.y;
            Qs[gA*4+2][mA] = qv.z; Qs[gA*4+3][mA] = qv.w;
            float4 kv = *(const float4*)(kbase + (size_t)(k0 + mA) * 512 + d0 + gA * 4);
            Ks[gA*4+0][mA] = kv.x; Ks[gA*4+1][mA] = kv.y;
            Ks[gA*4+2][mA] = kv.z; Ks[gA*4+3][mA] = kv.w;
        }
        #pragma unroll
        for (int r = 0; r < 2; r++) {
            int i2 = tid + r * 256;
            int ro = i2 >> 2, g = i2 & 3;
            int rr = rbase + ro;
            float4 ev = make_float4(0.f, 0.f, 0.f, 0.f);
            if (rr >= 0 && rr < L_)
                ev = *(const float4*)(E + (size_t)(rr + 1) * 512 + h * 64 + g * 4 + d0);
            Es[g*4+0][ro] = ev.x; Es[g*4+1][ro] = ev.y;
            Es[g*4+2][ro] = ev.z; Es[g*4+3][ro] = ev.w;
        }
        __syncthreads();
        int ebase = 4 * (tx - ty) + 60;
        #pragma unroll
        for (int dd = 0; dd < 16; dd++) {
            float a[4], kv[4], ev[7];
            #pragma unroll
            for (int i = 0; i < 4; i++) a[i] = Qs[dd][ty * 4 + i];
            #pragma unroll
            for (int j = 0; j < 4; j++) kv[j] = Ks[dd][tx * 4 + j];
            #pragma unroll
            for (int t = 0; t < 7; t++) ev[t] = Es[dd][ebase + t];
            #pragma unroll
            for (int i = 0; i < 4; i++)
                #pragma unroll
                for (int j = 0; j < 4; j++)
                    acc[i][j] += a[i] * (kv[j] + ev[j - i + 3]);
        }
        __syncthreads();
    }

    bool diag = (qt == kt);
    float* out = attn + ((size_t)bh * L_ + q0) * L_ + k0;
    #pragma unroll
    for (int i = 0; i < 4; i++) {
        float v[4];
        #pragma unroll
        for (int j = 0; j < 4; j++) v[j] = acc[i][j] * 0.125f;
        float4 o = make_float4(v[0], v[1], v[2], v[3]);
        *(float4*)(out + (size_t)(ty*4 + i) * L_ + tx*4) = o;

        // per-row stats across the 16 tx lanes (width-16 butterflies)
        int row = ty * 4 + i;
        float m = -1e30f;
        #pragma unroll
        for (int j = 0; j < 4; j++) {
            bool valid = !diag || (tx * 4 + j <= row);
            if (valid) m = fmaxf(m, v[j]);
        }
        #pragma unroll
        for (int off = 8; off > 0; off >>= 1)
            m = fmaxf(m, __shfl_xor_sync(0xffffffffu, m, off, 16));
        float s = 0.f;
        #pragma unroll
        for (int j = 0; j < 4; j++) {
            bool valid = !diag || (tx * 4 + j <= row);
            if (valid) s += __expf(v[j] - m);
        }
        #pragma unroll
        for (int off = 8; off > 0; off >>= 1)
            s += __shfl_xor_sync(0xffffffffu, s, off, 16);
        if (tx == 0)
            g_stats[((size_t)bh * NT_ + kt) * L_ + q0 + row] = make_float2(m, s);
    }
}

// ---------------------------------------------------------------------------
// Combine per-tile stats into per-row (max, 1/sum). One thread per row.
// ---------------------------------------------------------------------------
__global__ __launch_bounds__(256)
void statcomb_kernel()
{
    int p = blockIdx.x * 256 + threadIdx.x;     // p = bh*L + q
    if (p >= BH_ * L_) return;
    int bh = p / L_, q = p - bh * L_;
    int nt = q / 64 + 1;

    const float2* st = g_stats + (size_t)bh * NT_ * L_ + q;
    float M = -1e30f;
    for (int t = 0; t < nt; t++) M = fmaxf(M, st[(size_t)t * L_].x);
    float S = 0.f;
    for (int t = 0; t < nt; t++) {
        float2 v = st[(size_t)t * L_];
        S += v.y * __expf(v.x - M);
    }
    g_M[p] = M;
    g_I[p] = 1.f / S;
}

// ---------------------------------------------------------------------------
// Zero-fill the strict upper triangle (tiles beyond the diagonal tile).
// ---------------------------------------------------------------------------
__global__ __launch_bounds__(128)
void zerofill_kernel(float* __restrict__ attn)
{
    int p = blockIdx.x;
    int q = p % L_;
    int start4 = ((q / 64) + 1) * 16;           // (qt+1)*64 / 4
    float4* row = (float4*)(attn + (size_t)p * L_);
    float4 z = make_float4(0.f, 0.f, 0.f, 0.f);
    for (int i = start4 + threadIdx.x; i < L_/4; i += 128) row[i] = z;
}

// ---------------------------------------------------------------------------
// Fused normalize + AV: reads raw logits, p = exp(x-M)*invS (0 if k>q),
// writes p to attn (final output) and accumulates O_partial = p @ V.
// ---------------------------------------------------------------------------
__global__ __launch_bounds__(256)
void av_kernel(float* __restrict__ attn)
{
    int qt = blockIdx.x;
    int bh = blockIdx.y;
    int s  = blockIdx.z;
    int b = bh >> 3, h = bh & 7;
    int q0 = qt * 64;

    int kbeg = s * SPLITW;
    int kend = min(q0 + 64, kbeg + SPLITW);
    if (kbeg >= kend) return;

    __shared__ float As[16][68];
    __shared__ float Bs[16][68];
    __shared__ float sM[64];
    __shared__ float sI[64];
    int tid = threadIdx.x;
    int tx = tid & 15, ty = tid >> 4;
    float acc[4][4] = {};

    if (tid < 64) {
        sM[tid] = g_M[(size_t)bh * L_ + q0 + tid];
        sI[tid] = g_I[(size_t)bh * L_ + q0 + tid];
    }
    __syncthreads();

    float* arow        = attn + ((size_t)bh * L_ + q0) * L_;
    const float* vbase = g_vp + (size_t)b * L_ * 512 + h * 64;

    int mA = tid >> 2, gA = tid & 3;
    int kB = tid >> 4, gB = tid & 15;
    float Mr = sM[mA], Ir = sI[mA];
    int qrow = q0 + mA;

    for (int k0 = kbeg; k0 < kend; k0 += 16) {
        float4 xv = *(float4*)(arow + (size_t)mA * L_ + k0 + gA * 4);
        int kb = k0 + gA * 4;
        float4 p;
        p.x = (kb + 0 <= qrow) ? __expf(xv.x - Mr) * Ir : 0.f;
        p.y = (kb + 1 <= qrow) ? __expf(xv.y - Mr) * Ir : 0.f;
        p.z = (kb + 2 <= qrow) ? __expf(xv.z - Mr) * Ir : 0.f;
        p.w = (kb + 3 <= qrow) ? __expf(xv.w - Mr) * Ir : 0.f;
        *(float4*)(arow + (size_t)mA * L_ + k0 + gA * 4) = p;  // final attn out
        As[gA*4+0][mA] = p.x; As[gA*4+1][mA] = p.y;
        As[gA*4+2][mA] = p.z; As[gA*4+3][mA] = p.w;
        float4 vv = *(const float4*)(vbase + (size_t)(k0 + kB) * 512 + gB * 4);
        Bs[kB][gB*4+0] = vv.x; Bs[kB][gB*4+1] = vv.y;
        Bs[kB][gB*4+2] = vv.z; Bs[kB][gB*4+3] = vv.w;
        __syncthreads();
        #pragma unroll
        for (int kk = 0; kk < 16; kk++) {
            float a[4], bv[4];
            #pragma unroll
            for (int i = 0; i < 4; i++) a[i] = As[kk][ty * 4 + i];
            #pragma unroll
            for (int j = 0; j < 4; j++) bv[j] = Bs[kk][tx * 4 + j];
            #pragma unroll
            for (int i = 0; i < 4; i++)
                #pragma unroll
                for (int j = 0; j < 4; j++)
                    acc[i][j] += a[i] * bv[j];
        }
        __syncthreads();
    }

    float* op = g_op + (size_t)s * (BH_*L_*DH_) + ((size_t)bh * L_ + q0) * 64;
    #pragma unroll
    for (int i = 0; i < 4; i++) {
        float4 o = make_float4(acc[i][0], acc[i][1], acc[i][2], acc[i][3]);
        *(float4*)(op + (size_t)(ty*4 + i) * 64 + tx*4) = o;
    }
}

// ---------------------------------------------------------------------------
// out = (sum_s O_partial gathered across heads) @ Wo + bo
// ---------------------------------------------------------------------------
__global__ __launch_bounds__(256)
void oproj_kernel(const float* __restrict__ Wo, const float* __restrict__ bo,
                  float* __restrict__ out)
{
    __shared__ float As[16][68];
    __shared__ float Bs[16][68];
    int tid = threadIdx.x;
    int tx = tid & 15, ty = tid >> 4;
    int m0 = blockIdx.y * 64, n0 = blockIdx.x * 64;
    int b = m0 / L_;
    int l0 = m0 - b * L_;
    float acc[4][4] = {};

    int ns = (l0 + 64 + SPLITW - 1) / SPLITW;

    int mA = tid >> 2, gA = tid & 3;
    int kB = tid >> 4, gB = tid & 15;

    for (int k0 = 0; k0 < 512; k0 += 16) {
        int h = k0 >> 6, dh0 = k0 & 63;
        {
            const float* base = g_op + (((size_t)(b*8 + h) * L_ + l0 + mA) * 64 + dh0 + gA*4);
            float4 a4 = *(const float4*)(base);
            for (int ss = 1; ss < ns; ss++) {
                float4 t = *(const float4*)(base + (size_t)ss * (BH_*L_*DH_));
                a4.x += t.x; a4.y += t.y; a4.z += t.z; a4.w += t.w;
            }
            As[gA*4+0][mA] = a4.x; As[gA*4+1][mA] = a4.y;
            As[gA*4+2][mA] = a4.z; As[gA*4+3][mA] = a4.w;
        }
        float4 wv = *(const float4*)(Wo + (size_t)(k0 + kB) * 512 + n0 + gB * 4);
        Bs[kB][gB*4+0] = wv.x; Bs[kB][gB*4+1] = wv.y;
        Bs[kB][gB*4+2] = wv.z; Bs[kB][gB*4+3] = wv.w;
        __syncthreads();
        #pragma unroll
        for (int kk = 0; kk < 16; kk++) {
            float a[4], bv[4];
            #pragma unroll
            for (int i = 0; i < 4; i++) a[i] = As[kk][ty * 4 + i];
            #pragma unroll
            for (int j = 0; j < 4; j++) bv[j] = Bs[kk][tx * 4 + j];
            #pragma unroll
            for (int i = 0; i < 4; i++)
                #pragma unroll
                for (int j = 0; j < 4; j++)
                    acc[i][j] += a[i] * bv[j];
        }
        __syncthreads();
    }
    #pragma unroll
    for (int i = 0; i < 4; i++) {
        float4 o;
        o.x = acc[i][0] + bo[n0 + tx*4 + 0];
        o.y = acc[i][1] + bo[n0 + tx*4 + 1];
        o.z = acc[i][2] + bo[n0 + tx*4 + 2];
        o.w = acc[i][3] + bo[n0 + tx*4 + 3];
        *(float4*)(out + (size_t)(m0 + ty*4 + i) * 512 + n0 + tx*4) = o;
    }
}

// ---------------------------------------------------------------------------
extern "C" void kernel_launch(void* const* d_in, const int* in_sizes, int n_in,
                              void* d_out, int out_size)
{
    const float* q  = (const float*)d_in[0];
    const float* k  = (const float*)d_in[1];
    const float* v  = (const float*)d_in[2];
    const float* Wq = (const float*)d_in[4];
    const float* bq = (const float*)d_in[5];
    const float* Wk = (const float*)d_in[6];
    const float* bk = (const float*)d_in[7];
    const float* Wv = (const float*)d_in[8];
    const float* bv = (const float*)d_in[9];
    const float* E  = (const float*)d_in[10];
    const float* Wo = (const float*)d_in[11];
    const float* bo = (const float*)d_in[12];

    float* out_ptr  = (float*)d_out;
    float* attn_ptr = out_ptr + OUT_ELEMS;   // tuple order: (out, attn)

    qkv_proj_kernel<<<dim3(8, 60, 3), 256>>>(q, k, v, Wq, Wk, Wv, bq, bk, bv);
    zerofill_kernel<<<BH_ * L_, 128>>>(attn_ptr);
    scores_kernel<<<dim3(465, 16), 256>>>(E, attn_ptr);
    statcomb_kernel<<<(BH_ * L_ + 255) / 256, 256>>>();
    av_kernel<<<dim3(30, 16, NSPLIT), 256>>>(attn_ptr);
    oproj_kernel<<<dim3(8, 60), 256>>>(Wo, bo, out_ptr);
}